// round 13
// baseline (speedup 1.0000x reference)
#include <cuda_runtime.h>
#include <cuda_fp16.h>
#include <cstdint>

// ---------------------------------------------------------------------------
// Problem constants
// ---------------------------------------------------------------------------
#define TOKENS     512
#define DIM_K      8192
#define DIM_N      8192
#define HASH_SIZE  (1 << 22)
#define P_HASH     2038074743LL
#define HASH_RANGE 4193281LL          // HASH_SIZE - 1024 + 1

// GEMM: CTA tile 128(M) x 128(N) x 64(K-stage); 128 stages; 2 CTAs/SM
#define NSTG    128
#define THREADS 256
#define PIPE    3

// smem: A stage 128 rows x 128B = 16384; B stage 64 rows x 256B = 16384
#define OFF_A(s)   ((s) * 16384)
#define OFF_B(s)   (PIPE * 16384 + (s) * 16384)
#define SMEM_TOTAL (PIPE * 32768)     // 96 KB -> 2 CTAs/SM

// Scratch: fp16 copies. W materialized row-major [K][N].
__device__ __half g_xh[TOKENS * DIM_K];          // 8 MB
__device__ __half g_wh[(size_t)DIM_K * DIM_N];   // 128 MB

// ---------------------------------------------------------------------------
// Helpers
// ---------------------------------------------------------------------------
__device__ __forceinline__ uint32_t smem_to_u32(const void* p) {
    uint32_t a;
    asm("{ .reg .u64 t; cvta.to.shared.u64 t, %1; cvt.u32.u64 %0, t; }" : "=r"(a) : "l"(p));
    return a;
}
__device__ __forceinline__ void cp_async_16(uint32_t smem_dst, const void* gmem_src) {
    asm volatile("cp.async.cg.shared.global [%0], [%1], 16;\n" :: "r"(smem_dst), "l"(gmem_src));
}
__device__ __forceinline__ void cp_async_commit() { asm volatile("cp.async.commit_group;\n"); }
template <int N>
__device__ __forceinline__ void cp_async_wait() { asm volatile("cp.async.wait_group %0;\n" :: "n"(N)); }

__device__ __forceinline__ void ldsm_x4(uint32_t (&r)[4], uint32_t addr) {
    asm volatile("ldmatrix.sync.aligned.m8n8.x4.shared.b16 {%0,%1,%2,%3}, [%4];"
                 : "=r"(r[0]), "=r"(r[1]), "=r"(r[2]), "=r"(r[3]) : "r"(addr));
}
__device__ __forceinline__ void ldsm_x4_t(uint32_t (&r)[4], uint32_t addr) {
    asm volatile("ldmatrix.sync.aligned.m8n8.x4.trans.shared.b16 {%0,%1,%2,%3}, [%4];"
                 : "=r"(r[0]), "=r"(r[1]), "=r"(r[2]), "=r"(r[3]) : "r"(addr));
}
__device__ __forceinline__ void mma_f16(float (&c)[4], const uint32_t (&a)[4],
                                        uint32_t b0, uint32_t b1) {
    asm volatile("mma.sync.aligned.m16n8k16.row.col.f32.f16.f16.f32 "
                 "{%0,%1,%2,%3}, {%4,%5,%6,%7}, {%8,%9}, {%0,%1,%2,%3};"
                 : "+f"(c[0]), "+f"(c[1]), "+f"(c[2]), "+f"(c[3])
                 : "r"(a[0]), "r"(a[1]), "r"(a[2]), "r"(a[3]), "r"(b0), "r"(b1));
}

// Robust random_numbers decode (int64 vs int32 storage; values < 2^31)
__device__ __forceinline__ void decode_rn(const int* p,
                                          long long& R1, long long& R2, long long& R3) {
    if (p[1] == 0) { R1 = (unsigned)p[2]; R2 = (unsigned)p[4]; R3 = (unsigned)p[6]; }
    else           { R1 = (unsigned)p[1]; R2 = (unsigned)p[2]; R3 = (unsigned)p[3]; }
}

// ---------------------------------------------------------------------------
// Prep kernel: W hash-gather -> fp16 row-major; x -> fp16.
// STG.128 stores: thread handles 8 contiguous halves of one tile row.
// ---------------------------------------------------------------------------
#define NTILES (256 * 256)
#define XBLKS  2048

__global__ __launch_bounds__(128)
void prep_kernel(const float* __restrict__ hw,
                 const float* __restrict__ x,
                 const int* __restrict__ rn) {
    const int bid = blockIdx.x;
    const int tid = threadIdx.x;
    if (bid < NTILES) {
        const int kt = bid >> 8, nt = bid & 255;
        long long R1, R2, R3;
        decode_rn(rn, R1, R2, R3);
        long long v = ((long long)kt * R3 + (long long)nt * R2 + R1) % P_HASH;
        const int S = (int)(v % HASH_RANGE);
        // thread t: row r = t>>2, cols (t&3)*8 .. +8  (one 16B store)
        const int r = tid >> 2, c8 = (tid & 3) * 8;
        const float* src = hw + S + r * 32 + c8;
        __half h[8];
#pragma unroll
        for (int j = 0; j < 8; j++) h[j] = __float2half_rn(src[j]);
        *(uint4*)(g_wh + (size_t)(kt * 32 + r) * DIM_N + nt * 32 + c8) = *(const uint4*)h;
    } else {
        const int xb = bid - NTILES;
        const float4* src = (const float4*)x + (size_t)xb * 512;
        __half2* dst = (__half2*)g_xh + (size_t)xb * 1024;
#pragma unroll
        for (int j = 0; j < 4; j++) {
            const int i = tid + j * 128;
            const float4 v = src[i];
            dst[i * 2]     = __floats2half2_rn(v.x, v.y);
            dst[i * 2 + 1] = __floats2half2_rn(v.z, v.w);
        }
    }
}

// ---------------------------------------------------------------------------
// GEMM kernel: fp16 HMMA, R8 geometry (8 warps 2x4, warp tile 64x32),
// with cross-stage g0 fragment preload (barrier->LDSM->MMA chain removed).
// ---------------------------------------------------------------------------
__global__ __launch_bounds__(THREADS, 2)
void rz_f16_kernel(const float* __restrict__ bias,
                   float* __restrict__ out) {
    extern __shared__ char smem[];
    const uint32_t smem_base = smem_to_u32(smem);
    const int tid  = threadIdx.x;
    const int lane = tid & 31;
    const int wid  = tid >> 5;         // 0..7
    const int wm   = wid >> 2;         // 0..1
    const int wn   = wid & 3;          // 0..3
    const int m0   = blockIdx.y * 128;
    const int n0   = blockIdx.x * 128;

    // issue WITHOUT commit (caller commits, possibly empty, every iteration)
    auto issue = [&](int t) {
        const int slot = t % PIPE;
        const uint32_t As = smem_base + OFF_A(slot);
        const uint32_t Bs = smem_base + OFF_B(slot);
        const __half* xa = g_xh + (size_t)m0 * DIM_K + t * 64;
        const __half* wb = g_wh + (size_t)(t * 64) * DIM_N + n0;
#pragma unroll
        for (int u = 0; u < 4; u++) {              // A: 1024 16B chunks
            const int ch = tid + u * THREADS;
            const int m = ch >> 3, c = ch & 7;
            cp_async_16(As + m * 128 + ((c ^ (m & 7)) << 4),
                        xa + (size_t)m * DIM_K + c * 8);
        }
#pragma unroll
        for (int u = 0; u < 4; u++) {              // B: 1024 16B chunks
            const int ch = tid + u * THREADS;
            const int k = ch >> 4, c = ch & 15;
            cp_async_16(Bs + k * 256 + ((c ^ (k & 7)) << 4),
                        wb + (size_t)k * DIM_N + c * 8);
        }
    };

    float acc[4][4][4];
#pragma unroll
    for (int mt = 0; mt < 4; mt++)
#pragma unroll
        for (int nt = 0; nt < 4; nt++)
#pragma unroll
            for (int j = 0; j < 4; j++) acc[mt][nt][j] = 0.0f;

    // fragment lane addressing (constant across stages)
    const int ar = (lane & 15);            // A row within 16
    const int ac = (lane >> 4);            // A chunk parity
    const int bk = (lane & 7) + ((lane >> 3) & 1) * 8;   // B k within 16
    const int bc = (lane >> 4);            // B n-chunk parity
    const int arow0 = wm * 64 + ar;
    const int bn0   = wn * 4 + bc;

    uint32_t a0[4][4];                     // preloaded g0 A fragments
    uint32_t b0f[2][4];                    // preloaded g0 B fragments

    auto preload_g0 = [&](int t) {
        const int slot = t % PIPE;
        const uint32_t As = smem_base + OFF_A(slot);
        const uint32_t Bs = smem_base + OFF_B(slot);
#pragma unroll
        for (int mt = 0; mt < 4; mt++) {
            const int row = arow0 + mt * 16;
            ldsm_x4(a0[mt], As + row * 128 + ((ac ^ (row & 7)) << 4));
        }
#pragma unroll
        for (int ntp = 0; ntp < 2; ntp++) {
            const int nch = bn0 + ntp * 2;
            ldsm_x4_t(b0f[ntp], Bs + bk * 256 + ((nch ^ (bk & 7)) << 4));
        }
    };

    // Prologue: issue stages 0,1; preload stage-0 g0 fragments
    issue(0); cp_async_commit();
    issue(1); cp_async_commit();
    cp_async_wait<1>();                    // stage 0 resident
    __syncthreads();
    preload_g0(0);

    for (int t = 0; t < NSTG; t++) {
        __syncthreads();                   // stage t-1 reads done by all warps
        if (t + 2 < NSTG) issue(t + 2);    // rewrite slot (t+2)%3 = (t-1)%3
        cp_async_commit();                 // (possibly empty) keeps accounting fixed

        const int slot = t % PIPE;
        const uint32_t As = smem_base + OFF_A(slot);
        const uint32_t Bs = smem_base + OFF_B(slot);

        // ---- g0: MMAs on preloaded fragments (no LDSM dependency) ----
#pragma unroll
        for (int mt = 0; mt < 4; mt++)
#pragma unroll
            for (int nt = 0; nt < 4; nt++)
                mma_f16(acc[mt][nt], a0[mt],
                        b0f[nt >> 1][(nt & 1) * 2], b0f[nt >> 1][(nt & 1) * 2 + 1]);

        // ---- g1..g3: JIT fragments (overlap preceding MMAs) ----
#pragma unroll
        for (int g = 1; g < 4; g++) {
            uint32_t a[4][4];
#pragma unroll
            for (int mt = 0; mt < 4; mt++) {
                const int row = arow0 + mt * 16;
                const int ch  = g * 2 + ac;
                ldsm_x4(a[mt], As + row * 128 + ((ch ^ (row & 7)) << 4));
            }
            uint32_t bf[2][4];
            const int kk = g * 16 + bk;
#pragma unroll
            for (int ntp = 0; ntp < 2; ntp++) {
                const int nch = bn0 + ntp * 2;
                ldsm_x4_t(bf[ntp], Bs + kk * 256 + ((nch ^ (kk & 7)) << 4));
            }
#pragma unroll
            for (int mt = 0; mt < 4; mt++)
#pragma unroll
                for (int nt = 0; nt < 4; nt++)
                    mma_f16(acc[mt][nt], a[mt],
                            bf[nt >> 1][(nt & 1) * 2], bf[nt >> 1][(nt & 1) * 2 + 1]);
        }

        // ---- end of stage: t+1 now guaranteed resident; preload its g0 ----
        if (t + 1 < NSTG) {
            cp_async_wait<1>();            // in flight {t+1, t+2}; t+1 done
            preload_g0(t + 1);
        }
    }

    // Epilogue
#pragma unroll
    for (int mt = 0; mt < 4; mt++) {
#pragma unroll
        for (int nt = 0; nt < 4; nt++) {
            const int m = m0 + wm * 64 + mt * 16 + (lane >> 2);
            const int n = n0 + wn * 32 + nt * 8 + (lane & 3) * 2;
            const float2 b = *(const float2*)&bias[n];
            float2 o0, o1;
            o0.x = acc[mt][nt][0] + b.x;  o0.y = acc[mt][nt][1] + b.y;
            o1.x = acc[mt][nt][2] + b.x;  o1.y = acc[mt][nt][3] + b.y;
            *(float2*)&out[(size_t)m * DIM_N + n]       = o0;
            *(float2*)&out[(size_t)(m + 8) * DIM_N + n] = o1;
        }
    }
}

// ---------------------------------------------------------------------------
// Launch
// ---------------------------------------------------------------------------
extern "C" void kernel_launch(void* const* d_in, const int* in_sizes, int n_in,
                              void* d_out, int out_size) {
    const float* x    = (const float*)d_in[0];
    const float* hw   = (const float*)d_in[1];
    const float* bias = (const float*)d_in[2];
    const int*   rn   = (const int*)d_in[3];
    float*       out  = (float*)d_out;

    prep_kernel<<<NTILES + XBLKS, 128>>>(hw, x, rn);

    cudaFuncSetAttribute(rz_f16_kernel, cudaFuncAttributeMaxDynamicSharedMemorySize, SMEM_TOTAL);
    rz_f16_kernel<<<dim3(DIM_N / 128, TOKENS / 128), THREADS, SMEM_TOTAL>>>(bias, out);
}

// round 14
// speedup vs baseline: 1.1915x; 1.1915x over previous
#include <cuda_runtime.h>
#include <cuda_fp16.h>
#include <cstdint>

// ---------------------------------------------------------------------------
// Problem constants
// ---------------------------------------------------------------------------
#define TOKENS     512
#define DIM_K      8192
#define DIM_N      8192
#define HASH_SIZE  (1 << 22)
#define P_HASH     2038074743LL
#define HASH_RANGE 4193281LL          // HASH_SIZE - 1024 + 1

// GEMM: CTA tile 128(M) x 128(N) x 64(K-stage); 128 stages; 2 CTAs/SM
#define NSTG    128
#define THREADS 256
#define PIPE    3

// smem: A stage 128 rows x 128B = 16384; B stage 64 rows x 256B = 16384
#define OFF_A(s)   ((s) * 16384)
#define OFF_B(s)   (PIPE * 16384 + (s) * 16384)
#define SMEM_TOTAL (PIPE * 32768)     // 96 KB -> 2 CTAs/SM

// Scratch: fp16 copies. W materialized row-major [K][N].
__device__ __half g_xh[TOKENS * DIM_K];          // 8 MB
__device__ __half g_wh[(size_t)DIM_K * DIM_N];   // 128 MB

// ---------------------------------------------------------------------------
// Helpers
// ---------------------------------------------------------------------------
__device__ __forceinline__ uint32_t smem_to_u32(const void* p) {
    uint32_t a;
    asm("{ .reg .u64 t; cvta.to.shared.u64 t, %1; cvt.u32.u64 %0, t; }" : "=r"(a) : "l"(p));
    return a;
}
__device__ __forceinline__ void cp_async_16(uint32_t smem_dst, const void* gmem_src) {
    asm volatile("cp.async.cg.shared.global [%0], [%1], 16;\n" :: "r"(smem_dst), "l"(gmem_src));
}
__device__ __forceinline__ void cp_async_commit() { asm volatile("cp.async.commit_group;\n"); }
template <int N>
__device__ __forceinline__ void cp_async_wait() { asm volatile("cp.async.wait_group %0;\n" :: "n"(N)); }

__device__ __forceinline__ void ldsm_x4(uint32_t (&r)[4], uint32_t addr) {
    asm volatile("ldmatrix.sync.aligned.m8n8.x4.shared.b16 {%0,%1,%2,%3}, [%4];"
                 : "=r"(r[0]), "=r"(r[1]), "=r"(r[2]), "=r"(r[3]) : "r"(addr));
}
__device__ __forceinline__ void ldsm_x4_t(uint32_t (&r)[4], uint32_t addr) {
    asm volatile("ldmatrix.sync.aligned.m8n8.x4.trans.shared.b16 {%0,%1,%2,%3}, [%4];"
                 : "=r"(r[0]), "=r"(r[1]), "=r"(r[2]), "=r"(r[3]) : "r"(addr));
}
__device__ __forceinline__ void mma_f16(float (&c)[4], const uint32_t (&a)[4],
                                        uint32_t b0, uint32_t b1) {
    asm volatile("mma.sync.aligned.m16n8k16.row.col.f32.f16.f16.f32 "
                 "{%0,%1,%2,%3}, {%4,%5,%6,%7}, {%8,%9}, {%0,%1,%2,%3};"
                 : "+f"(c[0]), "+f"(c[1]), "+f"(c[2]), "+f"(c[3])
                 : "r"(a[0]), "r"(a[1]), "r"(a[2]), "r"(a[3]), "r"(b0), "r"(b1));
}

// Robust random_numbers decode (int64 vs int32 storage; values < 2^31)
__device__ __forceinline__ void decode_rn(const int* p,
                                          long long& R1, long long& R2, long long& R3) {
    if (p[1] == 0) { R1 = (unsigned)p[2]; R2 = (unsigned)p[4]; R3 = (unsigned)p[6]; }
    else           { R1 = (unsigned)p[1]; R2 = (unsigned)p[2]; R3 = (unsigned)p[3]; }
}

// ---------------------------------------------------------------------------
// Prep kernel: W hash-gather -> fp16 row-major; x -> fp16.
// Smem-staged: coalesced 4B gather loads (lane-consecutive) + 16B STG stores.
// ---------------------------------------------------------------------------
#define NTILES (256 * 256)
#define XBLKS  2048

__global__ __launch_bounds__(128)
void prep_kernel(const float* __restrict__ hw,
                 const float* __restrict__ x,
                 const int* __restrict__ rn) {
    __shared__ __half sh[1024];
    const int bid = blockIdx.x;
    const int tid = threadIdx.x;
    if (bid < NTILES) {
        const int kt = bid >> 8, nt = bid & 255;
        long long R1, R2, R3;
        decode_rn(rn, R1, R2, R3);
        long long v = ((long long)kt * R3 + (long long)nt * R2 + R1) % P_HASH;
        const int S = (int)(v % HASH_RANGE);
        const float* src = hw + S;
        // phase 1: fully coalesced loads (lane-consecutive 4B), convert to smem
#pragma unroll
        for (int j = 0; j < 8; j++) {
            const int e = tid + j * 128;
            sh[e] = __float2half_rn(src[e]);
        }
        __syncthreads();
        // phase 2: vectorized 16B stores; thread -> row r, cols c8..c8+8
        const int r = tid >> 2, c8 = (tid & 3) * 8;
        const uint4 vle = *(const uint4*)&sh[r * 32 + c8];
        *(uint4*)(g_wh + (size_t)(kt * 32 + r) * DIM_N + nt * 32 + c8) = vle;
    } else {
        const int xb = bid - NTILES;
        const float4* src = (const float4*)x + (size_t)xb * 512;
        __half2* dst = (__half2*)g_xh + (size_t)xb * 1024;
#pragma unroll
        for (int j = 0; j < 4; j++) {
            const int i = tid + j * 128;
            const float4 v = src[i];
            dst[i * 2]     = __floats2half2_rn(v.x, v.y);
            dst[i * 2 + 1] = __floats2half2_rn(v.z, v.w);
        }
    }
}

// ---------------------------------------------------------------------------
// GEMM kernel: fp16 HMMA (byte-identical to R8 best: 8 warps 2x4, warp tile
// 64x32, JIT fragments, PIPE=3, 2 CTAs/SM).
//   A smem: [m 128][k 64 halves] rows 128B, chunk swizzle c^(m&7)
//   B smem: [k 64][n 128 halves] rows 256B, chunk swizzle c^(k&7)
// ---------------------------------------------------------------------------
__global__ __launch_bounds__(THREADS, 2)
void rz_f16_kernel(const float* __restrict__ bias,
                   float* __restrict__ out) {
    extern __shared__ char smem[];
    const uint32_t smem_base = smem_to_u32(smem);
    const int tid  = threadIdx.x;
    const int lane = tid & 31;
    const int wid  = tid >> 5;         // 0..7
    const int wm   = wid >> 2;         // 0..1
    const int wn   = wid & 3;          // 0..3
    const int m0   = blockIdx.y * 128;
    const int n0   = blockIdx.x * 128;

    auto issue = [&](int t) {
        const int slot = t % PIPE;
        const uint32_t As = smem_base + OFF_A(slot);
        const uint32_t Bs = smem_base + OFF_B(slot);
        const __half* xa = g_xh + (size_t)m0 * DIM_K + t * 64;
        const __half* wb = g_wh + (size_t)(t * 64) * DIM_N + n0;
#pragma unroll
        for (int u = 0; u < 4; u++) {              // A: 1024 16B chunks
            const int ch = tid + u * THREADS;
            const int m = ch >> 3, c = ch & 7;
            cp_async_16(As + m * 128 + ((c ^ (m & 7)) << 4),
                        xa + (size_t)m * DIM_K + c * 8);
        }
#pragma unroll
        for (int u = 0; u < 4; u++) {              // B: 1024 16B chunks
            const int ch = tid + u * THREADS;
            const int k = ch >> 4, c = ch & 15;
            cp_async_16(Bs + k * 256 + ((c ^ (k & 7)) << 4),
                        wb + (size_t)k * DIM_N + c * 8);
        }
        cp_async_commit();
    };

    float acc[4][4][4];
#pragma unroll
    for (int mt = 0; mt < 4; mt++)
#pragma unroll
        for (int nt = 0; nt < 4; nt++)
#pragma unroll
            for (int j = 0; j < 4; j++) acc[mt][nt][j] = 0.0f;

    issue(0);
    issue(1);

    // fragment lane addressing (constant across stages)
    const int ar = (lane & 15);            // A row within 16
    const int ac = (lane >> 4);            // A chunk parity
    const int bk = (lane & 7) + ((lane >> 3) & 1) * 8;   // B k within 16
    const int bc = (lane >> 4);            // B n-chunk parity

    for (int t = 0; t < NSTG; t++) {
        cp_async_wait<1>();
        __syncthreads();
        if (t + 2 < NSTG) issue(t + 2);

        const int slot = t % PIPE;
        const uint32_t As = smem_base + OFF_A(slot);
        const uint32_t Bs = smem_base + OFF_B(slot);
#pragma unroll
        for (int g = 0; g < 4; g++) {
            uint32_t a[4][4];
#pragma unroll
            for (int mt = 0; mt < 4; mt++) {
                const int row = wm * 64 + mt * 16 + ar;
                const int ch  = g * 2 + ac;
                ldsm_x4(a[mt], As + row * 128 + ((ch ^ (row & 7)) << 4));
            }
            uint32_t bf[2][4];
#pragma unroll
            for (int ntp = 0; ntp < 2; ntp++) {
                const int k   = g * 16 + bk;
                const int nch = wn * 4 + ntp * 2 + bc;
                ldsm_x4_t(bf[ntp], Bs + k * 256 + ((nch ^ (k & 7)) << 4));
            }
#pragma unroll
            for (int mt = 0; mt < 4; mt++)
#pragma unroll
                for (int nt = 0; nt < 4; nt++)
                    mma_f16(acc[mt][nt], a[mt],
                            bf[nt >> 1][(nt & 1) * 2], bf[nt >> 1][(nt & 1) * 2 + 1]);
        }
    }

    // Epilogue
#pragma unroll
    for (int mt = 0; mt < 4; mt++) {
#pragma unroll
        for (int nt = 0; nt < 4; nt++) {
            const int m = m0 + wm * 64 + mt * 16 + (lane >> 2);
            const int n = n0 + wn * 32 + nt * 8 + (lane & 3) * 2;
            const float2 b = *(const float2*)&bias[n];
            float2 o0, o1;
            o0.x = acc[mt][nt][0] + b.x;  o0.y = acc[mt][nt][1] + b.y;
            o1.x = acc[mt][nt][2] + b.x;  o1.y = acc[mt][nt][3] + b.y;
            *(float2*)&out[(size_t)m * DIM_N + n]       = o0;
            *(float2*)&out[(size_t)(m + 8) * DIM_N + n] = o1;
        }
    }
}

// ---------------------------------------------------------------------------
// Launch
// ---------------------------------------------------------------------------
extern "C" void kernel_launch(void* const* d_in, const int* in_sizes, int n_in,
                              void* d_out, int out_size) {
    const float* x    = (const float*)d_in[0];
    const float* hw   = (const float*)d_in[1];
    const float* bias = (const float*)d_in[2];
    const int*   rn   = (const int*)d_in[3];
    float*       out  = (float*)d_out;

    prep_kernel<<<NTILES + XBLKS, 128>>>(hw, x, rn);

    cudaFuncSetAttribute(rz_f16_kernel, cudaFuncAttributeMaxDynamicSharedMemorySize, SMEM_TOTAL);
    rz_f16_kernel<<<dim3(DIM_N / 128, TOKENS / 128), THREADS, SMEM_TOTAL>>>(bias, out);
}

// round 15
// speedup vs baseline: 1.1971x; 1.0047x over previous
#include <cuda_runtime.h>
#include <cuda_fp16.h>
#include <cstdint>

// ---------------------------------------------------------------------------
// Problem constants
// ---------------------------------------------------------------------------
#define TOKENS     512
#define DIM_K      8192
#define DIM_N      8192
#define HASH_SIZE  (1 << 22)
#define P_HASH     2038074743LL
#define HASH_RANGE 4193281LL          // HASH_SIZE - 1024 + 1

// GEMM: CTA tile 128(M) x 128(N) x 64(K-stage); 128 stages; 2 CTAs/SM
#define NSTG    128
#define THREADS 256
#define PIPE    3

// smem: A stage 128 rows x 128B = 16384; B stage 64 rows x 256B = 16384
#define OFF_A(s)   ((s) * 16384)
#define OFF_B(s)   (PIPE * 16384 + (s) * 16384)
#define OFF_MBAR   (PIPE * 32768)          // 3 x 8B mbarriers
#define SMEM_TOTAL (OFF_MBAR + 64)         // 98368 -> still 2 CTAs/SM

// Scratch: fp16 copies. W materialized row-major [K][N].
__device__ __half g_xh[TOKENS * DIM_K];          // 8 MB
__device__ __half g_wh[(size_t)DIM_K * DIM_N];   // 128 MB

// ---------------------------------------------------------------------------
// Helpers
// ---------------------------------------------------------------------------
__device__ __forceinline__ uint32_t smem_to_u32(const void* p) {
    uint32_t a;
    asm("{ .reg .u64 t; cvta.to.shared.u64 t, %1; cvt.u32.u64 %0, t; }" : "=r"(a) : "l"(p));
    return a;
}
__device__ __forceinline__ void cp_async_16(uint32_t smem_dst, const void* gmem_src) {
    asm volatile("cp.async.cg.shared.global [%0], [%1], 16;\n" :: "r"(smem_dst), "l"(gmem_src));
}
__device__ __forceinline__ void cp_async_commit() { asm volatile("cp.async.commit_group;\n"); }
template <int N>
__device__ __forceinline__ void cp_async_wait() { asm volatile("cp.async.wait_group %0;\n" :: "n"(N)); }

#define MBARRIER_INIT(addr, cnt) \
    asm volatile("mbarrier.init.shared.b64 [%0], %1;" :: "r"((uint32_t)(addr)), "r"((uint32_t)(cnt)) : "memory")
#define MBARRIER_ARRIVE(addr) \
    asm volatile("mbarrier.arrive.shared.b64 _, [%0];" :: "r"((uint32_t)(addr)) : "memory")
#define MBARRIER_WAIT_PARITY(mbar_smem_addr, phase_parity) do { \
    uint32_t _mbar = (uint32_t)(mbar_smem_addr); \
    uint32_t _parity = (uint32_t)(phase_parity); \
    uint32_t _done; \
    asm volatile("{\n\t.reg .pred p;\n\t" \
        "mbarrier.try_wait.parity.acquire.cta.shared::cta.b64 p, [%1], %2;\n\t" \
        "selp.b32 %0, 1, 0, p;\n\t}" : "=r"(_done) : "r"(_mbar), "r"(_parity) : "memory"); \
    if (!_done) { \
        asm volatile("{\n\t.reg .pred P1;\n\t" \
            "WAIT_LOOP_%=:\n\t" \
            "mbarrier.try_wait.parity.acquire.cta.shared::cta.b64 P1, [%0], %1, 0x989680;\n\t" \
            "@P1 bra.uni WAIT_DONE_%=;\n\t" \
            "bra.uni WAIT_LOOP_%=;\n\t" \
            "WAIT_DONE_%=:\n\t}" :: "r"(_mbar), "r"(_parity) : "memory"); \
    } \
} while (0)

__device__ __forceinline__ void ldsm_x4(uint32_t (&r)[4], uint32_t addr) {
    asm volatile("ldmatrix.sync.aligned.m8n8.x4.shared.b16 {%0,%1,%2,%3}, [%4];"
                 : "=r"(r[0]), "=r"(r[1]), "=r"(r[2]), "=r"(r[3]) : "r"(addr));
}
__device__ __forceinline__ void ldsm_x4_t(uint32_t (&r)[4], uint32_t addr) {
    asm volatile("ldmatrix.sync.aligned.m8n8.x4.trans.shared.b16 {%0,%1,%2,%3}, [%4];"
                 : "=r"(r[0]), "=r"(r[1]), "=r"(r[2]), "=r"(r[3]) : "r"(addr));
}
__device__ __forceinline__ void mma_f16(float (&c)[4], const uint32_t (&a)[4],
                                        uint32_t b0, uint32_t b1) {
    asm volatile("mma.sync.aligned.m16n8k16.row.col.f32.f16.f16.f32 "
                 "{%0,%1,%2,%3}, {%4,%5,%6,%7}, {%8,%9}, {%0,%1,%2,%3};"
                 : "+f"(c[0]), "+f"(c[1]), "+f"(c[2]), "+f"(c[3])
                 : "r"(a[0]), "r"(a[1]), "r"(a[2]), "r"(a[3]), "r"(b0), "r"(b1));
}

// Robust random_numbers decode (int64 vs int32 storage; values < 2^31)
__device__ __forceinline__ void decode_rn(const int* p,
                                          long long& R1, long long& R2, long long& R3) {
    if (p[1] == 0) { R1 = (unsigned)p[2]; R2 = (unsigned)p[4]; R3 = (unsigned)p[6]; }
    else           { R1 = (unsigned)p[1]; R2 = (unsigned)p[2]; R3 = (unsigned)p[3]; }
}

// ---------------------------------------------------------------------------
// Prep kernel (R14): W hash-gather -> fp16 row-major; x -> fp16.
// ---------------------------------------------------------------------------
#define NTILES (256 * 256)
#define XBLKS  2048

__global__ __launch_bounds__(128)
void prep_kernel(const float* __restrict__ hw,
                 const float* __restrict__ x,
                 const int* __restrict__ rn) {
    __shared__ __half sh[1024];
    const int bid = blockIdx.x;
    const int tid = threadIdx.x;
    if (bid < NTILES) {
        const int kt = bid >> 8, nt = bid & 255;
        long long R1, R2, R3;
        decode_rn(rn, R1, R2, R3);
        long long v = ((long long)kt * R3 + (long long)nt * R2 + R1) % P_HASH;
        const int S = (int)(v % HASH_RANGE);
        const float* src = hw + S;
#pragma unroll
        for (int j = 0; j < 8; j++) {
            const int e = tid + j * 128;
            sh[e] = __float2half_rn(src[e]);
        }
        __syncthreads();
        const int r = tid >> 2, c8 = (tid & 3) * 8;
        const uint4 vle = *(const uint4*)&sh[r * 32 + c8];
        *(uint4*)(g_wh + (size_t)(kt * 32 + r) * DIM_N + nt * 32 + c8) = vle;
    } else {
        const int xb = bid - NTILES;
        const float4* src = (const float4*)x + (size_t)xb * 512;
        __half2* dst = (__half2*)g_xh + (size_t)xb * 1024;
#pragma unroll
        for (int j = 0; j < 4; j++) {
            const int i = tid + j * 128;
            const float4 v = src[i];
            dst[i * 2]     = __floats2half2_rn(v.x, v.y);
            dst[i * 2 + 1] = __floats2half2_rn(v.z, v.w);
        }
    }
}

// ---------------------------------------------------------------------------
// GEMM kernel: fp16 HMMA (R8 geometry: 8 warps 2x4, warp tile 64x32, JIT
// fragments, PIPE=3, 2 CTAs/SM) with the per-stage __syncthreads rendezvous
// replaced by a 3-slot mbarrier producer/consumer chain:
//   arrive(W[t%3]) at end of stage t  (release; also certifies slot t+1,
//   since each thread's cp_async_wait<1> precedes it)
//   wait(W[(t+2)%3], parity (t/3)&1) at start of stage t (acquire)
// -> warps may skew by up to one full stage instead of meeting every stage.
// ---------------------------------------------------------------------------
__global__ __launch_bounds__(THREADS, 2)
void rz_f16_kernel(const float* __restrict__ bias,
                   float* __restrict__ out) {
    extern __shared__ char smem[];
    const uint32_t smem_base = smem_to_u32(smem);
    const int tid  = threadIdx.x;
    const int lane = tid & 31;
    const int wid  = tid >> 5;         // 0..7
    const int wm   = wid >> 2;         // 0..1
    const int wn   = wid & 3;          // 0..3
    const int m0   = blockIdx.y * 128;
    const int n0   = blockIdx.x * 128;
    const uint32_t mb = smem_base + OFF_MBAR;

    if (tid == 0) {
        MBARRIER_INIT(mb + 0, THREADS);
        MBARRIER_INIT(mb + 8, THREADS);
        MBARRIER_INIT(mb + 16, THREADS);
    }
    __syncthreads();                   // one-time: mbarriers visible

    auto issue = [&](int t) {
        const int slot = t % PIPE;
        const uint32_t As = smem_base + OFF_A(slot);
        const uint32_t Bs = smem_base + OFF_B(slot);
        const __half* xa = g_xh + (size_t)m0 * DIM_K + t * 64;
        const __half* wb = g_wh + (size_t)(t * 64) * DIM_N + n0;
#pragma unroll
        for (int u = 0; u < 4; u++) {              // A: 1024 16B chunks
            const int ch = tid + u * THREADS;
            const int m = ch >> 3, c = ch & 7;
            cp_async_16(As + m * 128 + ((c ^ (m & 7)) << 4),
                        xa + (size_t)m * DIM_K + c * 8);
        }
#pragma unroll
        for (int u = 0; u < 4; u++) {              // B: 1024 16B chunks
            const int ch = tid + u * THREADS;
            const int k = ch >> 4, c = ch & 15;
            cp_async_16(Bs + k * 256 + ((c ^ (k & 7)) << 4),
                        wb + (size_t)k * DIM_N + c * 8);
        }
    };

    float acc[4][4][4];
#pragma unroll
    for (int mt = 0; mt < 4; mt++)
#pragma unroll
        for (int nt = 0; nt < 4; nt++)
#pragma unroll
            for (int j = 0; j < 4; j++) acc[mt][nt][j] = 0.0f;

    // fragment lane addressing (constant across stages)
    const int ar = (lane & 15);            // A row within 16
    const int ac = (lane >> 4);            // A chunk parity
    const int bk = (lane & 7) + ((lane >> 3) & 1) * 8;   // B k within 16
    const int bc = (lane >> 4);            // B n-chunk parity

    // Prologue: stages 0,1 in flight; certify slot 0 and arrive W[2]
    issue(0); cp_async_commit();
    issue(1); cp_async_commit();
    cp_async_wait<1>();                    // slot 0 complete (this thread)
    MBARRIER_ARRIVE(mb + 16);              // W[2] phase 0

    for (int t = 0; t < NSTG; t++) {
        const int wslot = (t + 2) % 3;     // == (t-1)%3: slot being rewritten
        const int wpar  = (t / 3) & 1;
        MBARRIER_WAIT_PARITY(mb + wslot * 8, wpar);  // readers done + slot t visible

        if (t + 2 < NSTG) issue(t + 2);
        cp_async_commit();                 // possibly empty: fixed group accounting

        const int slot = t % PIPE;
        const uint32_t As = smem_base + OFF_A(slot);
        const uint32_t Bs = smem_base + OFF_B(slot);
#pragma unroll
        for (int g = 0; g < 4; g++) {
            uint32_t a[4][4];
#pragma unroll
            for (int mt = 0; mt < 4; mt++) {
                const int row = wm * 64 + mt * 16 + ar;
                const int ch  = g * 2 + ac;
                ldsm_x4(a[mt], As + row * 128 + ((ch ^ (row & 7)) << 4));
            }
            uint32_t bf[2][4];
#pragma unroll
            for (int ntp = 0; ntp < 2; ntp++) {
                const int k   = g * 16 + bk;
                const int nch = wn * 4 + ntp * 2 + bc;
                ldsm_x4_t(bf[ntp], Bs + k * 256 + ((nch ^ (k & 7)) << 4));
            }
#pragma unroll
            for (int mt = 0; mt < 4; mt++)
#pragma unroll
                for (int nt = 0; nt < 4; nt++)
                    mma_f16(acc[mt][nt], a[mt],
                            bf[nt >> 1][(nt & 1) * 2], bf[nt >> 1][(nt & 1) * 2 + 1]);
        }

        cp_async_wait<1>();                // slot t+1 complete (this thread)
        MBARRIER_ARRIVE(mb + slot * 8);    // release: reads of slot t done + t+1 certified
    }

    // Epilogue
#pragma unroll
    for (int mt = 0; mt < 4; mt++) {
#pragma unroll
        for (int nt = 0; nt < 4; nt++) {
            const int m = m0 + wm * 64 + mt * 16 + (lane >> 2);
            const int n = n0 + wn * 32 + nt * 8 + (lane & 3) * 2;
            const float2 b = *(const float2*)&bias[n];
            float2 o0, o1;
            o0.x = acc[mt][nt][0] + b.x;  o0.y = acc[mt][nt][1] + b.y;
            o1.x = acc[mt][nt][2] + b.x;  o1.y = acc[mt][nt][3] + b.y;
            *(float2*)&out[(size_t)m * DIM_N + n]       = o0;
            *(float2*)&out[(size_t)(m + 8) * DIM_N + n] = o1;
        }
    }
}

// ---------------------------------------------------------------------------
// Launch
// ---------------------------------------------------------------------------
extern "C" void kernel_launch(void* const* d_in, const int* in_sizes, int n_in,
                              void* d_out, int out_size) {
    const float* x    = (const float*)d_in[0];
    const float* hw   = (const float*)d_in[1];
    const float* bias = (const float*)d_in[2];
    const int*   rn   = (const int*)d_in[3];
    float*       out  = (float*)d_out;

    prep_kernel<<<NTILES + XBLKS, 128>>>(hw, x, rn);

    cudaFuncSetAttribute(rz_f16_kernel, cudaFuncAttributeMaxDynamicSharedMemorySize, SMEM_TOTAL);
    rz_f16_kernel<<<dim3(DIM_N / 128, TOKENS / 128), THREADS, SMEM_TOTAL>>>(bias, out);
}

// round 16
// speedup vs baseline: 1.2003x; 1.0027x over previous
#include <cuda_runtime.h>
#include <cuda_fp16.h>
#include <cstdint>

// ---------------------------------------------------------------------------
// Problem constants
// ---------------------------------------------------------------------------
#define TOKENS     512
#define DIM_K      8192
#define DIM_N      8192
#define HASH_SIZE  (1 << 22)
#define P_HASH     2038074743LL
#define HASH_RANGE 4193281LL          // HASH_SIZE - 1024 + 1

// GEMM: CTA tile 128(M) x 128(N) x 64(K-stage); 128 stages; 2 CTAs/SM
#define NSTG    128
#define THREADS 256
#define PIPE    3

// smem: A stage 128 rows x 128B = 16384; B stage 64 rows x 256B = 16384
#define OFF_A(s)   ((s) * 16384)
#define OFF_B(s)   (PIPE * 16384 + (s) * 16384)
#define OFF_MBAR   (PIPE * 32768)          // 3 x 8B mbarriers
#define SMEM_TOTAL (OFF_MBAR + 64)         // 98368 -> still 2 CTAs/SM

// Scratch: fp16 copies. W materialized row-major [K][N].
__device__ __half g_xh[TOKENS * DIM_K];          // 8 MB
__device__ __half g_wh[(size_t)DIM_K * DIM_N];   // 128 MB

// ---------------------------------------------------------------------------
// Helpers
// ---------------------------------------------------------------------------
__device__ __forceinline__ uint32_t smem_to_u32(const void* p) {
    uint32_t a;
    asm("{ .reg .u64 t; cvta.to.shared.u64 t, %1; cvt.u32.u64 %0, t; }" : "=r"(a) : "l"(p));
    return a;
}
__device__ __forceinline__ void cp_async_16(uint32_t smem_dst, const void* gmem_src) {
    asm volatile("cp.async.cg.shared.global [%0], [%1], 16;\n" :: "r"(smem_dst), "l"(gmem_src));
}
__device__ __forceinline__ void cp_async_commit() { asm volatile("cp.async.commit_group;\n"); }
template <int N>
__device__ __forceinline__ void cp_async_wait() { asm volatile("cp.async.wait_group %0;\n" :: "n"(N)); }

#define MBARRIER_INIT(addr, cnt) \
    asm volatile("mbarrier.init.shared.b64 [%0], %1;" :: "r"((uint32_t)(addr)), "r"((uint32_t)(cnt)) : "memory")
#define MBARRIER_ARRIVE(addr) \
    asm volatile("mbarrier.arrive.shared.b64 _, [%0];" :: "r"((uint32_t)(addr)) : "memory")
#define MBARRIER_WAIT_PARITY(mbar_smem_addr, phase_parity) do { \
    uint32_t _mbar = (uint32_t)(mbar_smem_addr); \
    uint32_t _parity = (uint32_t)(phase_parity); \
    uint32_t _done; \
    asm volatile("{\n\t.reg .pred p;\n\t" \
        "mbarrier.try_wait.parity.acquire.cta.shared::cta.b64 p, [%1], %2;\n\t" \
        "selp.b32 %0, 1, 0, p;\n\t}" : "=r"(_done) : "r"(_mbar), "r"(_parity) : "memory"); \
    if (!_done) { \
        asm volatile("{\n\t.reg .pred P1;\n\t" \
            "WAIT_LOOP_%=:\n\t" \
            "mbarrier.try_wait.parity.acquire.cta.shared::cta.b64 P1, [%0], %1, 0x989680;\n\t" \
            "@P1 bra.uni WAIT_DONE_%=;\n\t" \
            "bra.uni WAIT_LOOP_%=;\n\t" \
            "WAIT_DONE_%=:\n\t}" :: "r"(_mbar), "r"(_parity) : "memory"); \
    } \
} while (0)

__device__ __forceinline__ void ldsm_x4(uint32_t (&r)[4], uint32_t addr) {
    asm volatile("ldmatrix.sync.aligned.m8n8.x4.shared.b16 {%0,%1,%2,%3}, [%4];"
                 : "=r"(r[0]), "=r"(r[1]), "=r"(r[2]), "=r"(r[3]) : "r"(addr));
}
__device__ __forceinline__ void ldsm_x4_t(uint32_t (&r)[4], uint32_t addr) {
    asm volatile("ldmatrix.sync.aligned.m8n8.x4.trans.shared.b16 {%0,%1,%2,%3}, [%4];"
                 : "=r"(r[0]), "=r"(r[1]), "=r"(r[2]), "=r"(r[3]) : "r"(addr));
}
__device__ __forceinline__ void mma_f16(float (&c)[4], const uint32_t (&a)[4],
                                        uint32_t b0, uint32_t b1) {
    asm volatile("mma.sync.aligned.m16n8k16.row.col.f32.f16.f16.f32 "
                 "{%0,%1,%2,%3}, {%4,%5,%6,%7}, {%8,%9}, {%0,%1,%2,%3};"
                 : "+f"(c[0]), "+f"(c[1]), "+f"(c[2]), "+f"(c[3])
                 : "r"(a[0]), "r"(a[1]), "r"(a[2]), "r"(a[3]), "r"(b0), "r"(b1));
}

// Robust random_numbers decode (int64 vs int32 storage; values < 2^31)
__device__ __forceinline__ void decode_rn(const int* p,
                                          long long& R1, long long& R2, long long& R3) {
    if (p[1] == 0) { R1 = (unsigned)p[2]; R2 = (unsigned)p[4]; R3 = (unsigned)p[6]; }
    else           { R1 = (unsigned)p[1]; R2 = (unsigned)p[2]; R3 = (unsigned)p[3]; }
}

// ---------------------------------------------------------------------------
// Prep kernel: W hash-gather -> fp16 row-major with FULL 128B row writes.
// Each W block (256 thr) handles TWO adjacent n-tiles (same kt): gather both,
// stage in smem [32][64] halves, write 32 rows x 128B fully-coalesced.
//   blocks [0, 32768): W pair-tiles
//   blocks [32768, +1024): x conversion (1024 float4 each, 256 thr)
// ---------------------------------------------------------------------------
#define WBLKS (256 * 128)    // 32768: kt 0..255, j 0..127 (nt pair = 2j, 2j+1)
#define XBLKS 1024

__global__ __launch_bounds__(256)
void prep_kernel(const float* __restrict__ hw,
                 const float* __restrict__ x,
                 const int* __restrict__ rn) {
    __shared__ __half sh[32][64];
    const int bid = blockIdx.x;
    const int tid = threadIdx.x;
    if (bid < WBLKS) {
        const int kt = bid >> 7, j = bid & 127;
        long long R1, R2, R3;
        decode_rn(rn, R1, R2, R3);
        long long v0 = ((long long)kt * R3 + (long long)(2 * j) * R2 + R1) % P_HASH;
        long long v1 = ((long long)kt * R3 + (long long)(2 * j + 1) * R2 + R1) % P_HASH;
        const int S0 = (int)(v0 % HASH_RANGE);
        const int S1 = (int)(v1 % HASH_RANGE);
        // phase 1: coalesced gather of both 1024-float tiles -> smem halves
#pragma unroll
        for (int i = 0; i < 4; i++) {
            const int e = tid + i * 256;           // 0..1023 = k*32 + n
            sh[e >> 5][e & 31]        = __float2half_rn(hw[S0 + e]);
            sh[e >> 5][32 + (e & 31)] = __float2half_rn(hw[S1 + e]);
        }
        __syncthreads();
        // phase 2: 256 chunks of 16B = 32 rows x 128B, fully coalesced
        const int r = tid >> 3, c8 = (tid & 7) * 8;
        const uint4 vle = *(const uint4*)&sh[r][c8];
        *(uint4*)(g_wh + (size_t)(kt * 32 + r) * DIM_N + j * 64 + c8) = vle;
    } else {
        const int xb = bid - WBLKS;
        const float4* src = (const float4*)x + (size_t)xb * 1024;
        __half2* dst = (__half2*)g_xh + (size_t)xb * 2048;
#pragma unroll
        for (int i = 0; i < 4; i++) {
            const int e = tid + i * 256;
            const float4 v = src[e];
            dst[e * 2]     = __floats2half2_rn(v.x, v.y);
            dst[e * 2 + 1] = __floats2half2_rn(v.z, v.w);
        }
    }
}

// ---------------------------------------------------------------------------
// GEMM kernel: fp16 HMMA (R8 geometry: 8 warps 2x4, warp tile 64x32, JIT
// fragments, PIPE=3, 2 CTAs/SM) with 3-slot mbarrier producer/consumer chain
// (R15): arrive(W[t%3]) at stage end releases slot-t reads AND certifies
// slot t+1 (cp_async_wait<1> precedes it); wait acquires both.
// ---------------------------------------------------------------------------
__global__ __launch_bounds__(THREADS, 2)
void rz_f16_kernel(const float* __restrict__ bias,
                   float* __restrict__ out) {
    extern __shared__ char smem[];
    const uint32_t smem_base = smem_to_u32(smem);
    const int tid  = threadIdx.x;
    const int lane = tid & 31;
    const int wid  = tid >> 5;         // 0..7
    const int wm   = wid >> 2;         // 0..1
    const int wn   = wid & 3;          // 0..3
    const int m0   = blockIdx.y * 128;
    const int n0   = blockIdx.x * 128;
    const uint32_t mb = smem_base + OFF_MBAR;

    if (tid == 0) {
        MBARRIER_INIT(mb + 0, THREADS);
        MBARRIER_INIT(mb + 8, THREADS);
        MBARRIER_INIT(mb + 16, THREADS);
    }
    __syncthreads();                   // one-time: mbarriers visible

    auto issue = [&](int t) {
        const int slot = t % PIPE;
        const uint32_t As = smem_base + OFF_A(slot);
        const uint32_t Bs = smem_base + OFF_B(slot);
        const __half* xa = g_xh + (size_t)m0 * DIM_K + t * 64;
        const __half* wb = g_wh + (size_t)(t * 64) * DIM_N + n0;
#pragma unroll
        for (int u = 0; u < 4; u++) {              // A: 1024 16B chunks
            const int ch = tid + u * THREADS;
            const int m = ch >> 3, c = ch & 7;
            cp_async_16(As + m * 128 + ((c ^ (m & 7)) << 4),
                        xa + (size_t)m * DIM_K + c * 8);
        }
#pragma unroll
        for (int u = 0; u < 4; u++) {              // B: 1024 16B chunks
            const int ch = tid + u * THREADS;
            const int k = ch >> 4, c = ch & 15;
            cp_async_16(Bs + k * 256 + ((c ^ (k & 7)) << 4),
                        wb + (size_t)k * DIM_N + c * 8);
        }
    };

    float acc[4][4][4];
#pragma unroll
    for (int mt = 0; mt < 4; mt++)
#pragma unroll
        for (int nt = 0; nt < 4; nt++)
#pragma unroll
            for (int j = 0; j < 4; j++) acc[mt][nt][j] = 0.0f;

    // fragment lane addressing (constant across stages)
    const int ar = (lane & 15);            // A row within 16
    const int ac = (lane >> 4);            // A chunk parity
    const int bk = (lane & 7) + ((lane >> 3) & 1) * 8;   // B k within 16
    const int bc = (lane >> 4);            // B n-chunk parity

    // Prologue: stages 0,1 in flight; certify slot 0 and arrive W[2]
    issue(0); cp_async_commit();
    issue(1); cp_async_commit();
    cp_async_wait<1>();                    // slot 0 complete (this thread)
    MBARRIER_ARRIVE(mb + 16);              // W[2] phase 0

    for (int t = 0; t < NSTG; t++) {
        const int wslot = (t + 2) % 3;     // == (t-1)%3: slot being rewritten
        const int wpar  = (t / 3) & 1;
        MBARRIER_WAIT_PARITY(mb + wslot * 8, wpar);  // readers done + slot t visible

        if (t + 2 < NSTG) issue(t + 2);
        cp_async_commit();                 // possibly empty: fixed group accounting

        const int slot = t % PIPE;
        const uint32_t As = smem_base + OFF_A(slot);
        const uint32_t Bs = smem_base + OFF_B(slot);
#pragma unroll
        for (int g = 0; g < 4; g++) {
            uint32_t a[4][4];
#pragma unroll
            for (int mt = 0; mt < 4; mt++) {
                const int row = wm * 64 + mt * 16 + ar;
                const int ch  = g * 2 + ac;
                ldsm_x4(a[mt], As + row * 128 + ((ch ^ (row & 7)) << 4));
            }
            uint32_t bf[2][4];
#pragma unroll
            for (int ntp = 0; ntp < 2; ntp++) {
                const int k   = g * 16 + bk;
                const int nch = wn * 4 + ntp * 2 + bc;
                ldsm_x4_t(bf[ntp], Bs + k * 256 + ((nch ^ (k & 7)) << 4));
            }
#pragma unroll
            for (int mt = 0; mt < 4; mt++)
#pragma unroll
                for (int nt = 0; nt < 4; nt++)
                    mma_f16(acc[mt][nt], a[mt],
                            bf[nt >> 1][(nt & 1) * 2], bf[nt >> 1][(nt & 1) * 2 + 1]);
        }

        cp_async_wait<1>();                // slot t+1 complete (this thread)
        MBARRIER_ARRIVE(mb + slot * 8);    // release: slot-t reads done + t+1 certified
    }

    // Epilogue
#pragma unroll
    for (int mt = 0; mt < 4; mt++) {
#pragma unroll
        for (int nt = 0; nt < 4; nt++) {
            const int m = m0 + wm * 64 + mt * 16 + (lane >> 2);
            const int n = n0 + wn * 32 + nt * 8 + (lane & 3) * 2;
            const float2 b = *(const float2*)&bias[n];
            float2 o0, o1;
            o0.x = acc[mt][nt][0] + b.x;  o0.y = acc[mt][nt][1] + b.y;
            o1.x = acc[mt][nt][2] + b.x;  o1.y = acc[mt][nt][3] + b.y;
            *(float2*)&out[(size_t)m * DIM_N + n]       = o0;
            *(float2*)&out[(size_t)(m + 8) * DIM_N + n] = o1;
        }
    }
}

// ---------------------------------------------------------------------------
// Launch
// ---------------------------------------------------------------------------
extern "C" void kernel_launch(void* const* d_in, const int* in_sizes, int n_in,
                              void* d_out, int out_size) {
    const float* x    = (const float*)d_in[0];
    const float* hw   = (const float*)d_in[1];
    const float* bias = (const float*)d_in[2];
    const int*   rn   = (const int*)d_in[3];
    float*       out  = (float*)d_out;

    prep_kernel<<<WBLKS + XBLKS, 256>>>(hw, x, rn);

    cudaFuncSetAttribute(rz_f16_kernel, cudaFuncAttributeMaxDynamicSharedMemorySize, SMEM_TOTAL);
    rz_f16_kernel<<<dim3(DIM_N / 128, TOKENS / 128), THREADS, SMEM_TOTAL>>>(bias, out);
}

// round 17
// speedup vs baseline: 1.2179x; 1.0147x over previous
#include <cuda_runtime.h>
#include <cuda_fp16.h>
#include <cstdint>

// ---------------------------------------------------------------------------
// Problem constants
// ---------------------------------------------------------------------------
#define TOKENS     512
#define DIM_K      8192
#define DIM_N      8192
#define HASH_SIZE  (1 << 22)
#define P_HASH     2038074743LL
#define HASH_RANGE 4193281LL          // HASH_SIZE - 1024 + 1

// GEMM: CTA tile 128(M) x 128(N) x 64(K-stage); 128 stages; 2 CTAs/SM
#define NSTG    128
#define THREADS 256
#define PIPE    3

// smem: A stage 128 rows x 128B = 16384; B stage 64 rows x 256B = 16384
#define OFF_A(s)   ((s) * 16384)
#define OFF_B(s)   (PIPE * 16384 + (s) * 16384)
#define OFF_MBAR   (PIPE * 32768)          // 3 x 8B mbarriers
#define SMEM_TOTAL (OFF_MBAR + 64)         // 98368 -> still 2 CTAs/SM

// Scratch: fp16 hashed array, fp16 x, materialized fp16 W row-major [K][N].
__device__ __half g_hwf16[HASH_SIZE];            // 8 MB
__device__ __half g_xh[TOKENS * DIM_K];          // 8 MB
__device__ __half g_wh[(size_t)DIM_K * DIM_N];   // 128 MB

// ---------------------------------------------------------------------------
// Helpers
// ---------------------------------------------------------------------------
__device__ __forceinline__ uint32_t smem_to_u32(const void* p) {
    uint32_t a;
    asm("{ .reg .u64 t; cvta.to.shared.u64 t, %1; cvt.u32.u64 %0, t; }" : "=r"(a) : "l"(p));
    return a;
}
__device__ __forceinline__ void cp_async_16(uint32_t smem_dst, const void* gmem_src) {
    asm volatile("cp.async.cg.shared.global [%0], [%1], 16;\n" :: "r"(smem_dst), "l"(gmem_src));
}
__device__ __forceinline__ void cp_async_commit() { asm volatile("cp.async.commit_group;\n"); }
template <int N>
__device__ __forceinline__ void cp_async_wait() { asm volatile("cp.async.wait_group %0;\n" :: "n"(N)); }

#define MBARRIER_INIT(addr, cnt) \
    asm volatile("mbarrier.init.shared.b64 [%0], %1;" :: "r"((uint32_t)(addr)), "r"((uint32_t)(cnt)) : "memory")
#define MBARRIER_ARRIVE(addr) \
    asm volatile("mbarrier.arrive.shared.b64 _, [%0];" :: "r"((uint32_t)(addr)) : "memory")
#define MBARRIER_WAIT_PARITY(mbar_smem_addr, phase_parity) do { \
    uint32_t _mbar = (uint32_t)(mbar_smem_addr); \
    uint32_t _parity = (uint32_t)(phase_parity); \
    uint32_t _done; \
    asm volatile("{\n\t.reg .pred p;\n\t" \
        "mbarrier.try_wait.parity.acquire.cta.shared::cta.b64 p, [%1], %2;\n\t" \
        "selp.b32 %0, 1, 0, p;\n\t}" : "=r"(_done) : "r"(_mbar), "r"(_parity) : "memory"); \
    if (!_done) { \
        asm volatile("{\n\t.reg .pred P1;\n\t" \
            "WAIT_LOOP_%=:\n\t" \
            "mbarrier.try_wait.parity.acquire.cta.shared::cta.b64 P1, [%0], %1, 0x989680;\n\t" \
            "@P1 bra.uni WAIT_DONE_%=;\n\t" \
            "bra.uni WAIT_LOOP_%=;\n\t" \
            "WAIT_DONE_%=:\n\t}" :: "r"(_mbar), "r"(_parity) : "memory"); \
    } \
} while (0)

__device__ __forceinline__ void ldsm_x4(uint32_t (&r)[4], uint32_t addr) {
    asm volatile("ldmatrix.sync.aligned.m8n8.x4.shared.b16 {%0,%1,%2,%3}, [%4];"
                 : "=r"(r[0]), "=r"(r[1]), "=r"(r[2]), "=r"(r[3]) : "r"(addr));
}
__device__ __forceinline__ void ldsm_x4_t(uint32_t (&r)[4], uint32_t addr) {
    asm volatile("ldmatrix.sync.aligned.m8n8.x4.trans.shared.b16 {%0,%1,%2,%3}, [%4];"
                 : "=r"(r[0]), "=r"(r[1]), "=r"(r[2]), "=r"(r[3]) : "r"(addr));
}
__device__ __forceinline__ void mma_f16(float (&c)[4], const uint32_t (&a)[4],
                                        uint32_t b0, uint32_t b1) {
    asm volatile("mma.sync.aligned.m16n8k16.row.col.f32.f16.f16.f32 "
                 "{%0,%1,%2,%3}, {%4,%5,%6,%7}, {%8,%9}, {%0,%1,%2,%3};"
                 : "+f"(c[0]), "+f"(c[1]), "+f"(c[2]), "+f"(c[3])
                 : "r"(a[0]), "r"(a[1]), "r"(a[2]), "r"(a[3]), "r"(b0), "r"(b1));
}

// Robust random_numbers decode (int64 vs int32 storage; values < 2^31)
__device__ __forceinline__ void decode_rn(const int* p,
                                          long long& R1, long long& R2, long long& R3) {
    if (p[1] == 0) { R1 = (unsigned)p[2]; R2 = (unsigned)p[4]; R3 = (unsigned)p[6]; }
    else           { R1 = (unsigned)p[1]; R2 = (unsigned)p[2]; R3 = (unsigned)p[3]; }
}

// ---------------------------------------------------------------------------
// Kernel 0: convert hashed array -> fp16 (g_hwf16) and x -> fp16 (g_xh).
//   blocks [0, 2048): hashed array, 256 thr x 8 floats (vectorized)
//   blocks [2048, 3072): x, 256 thr x 4 float4
// ---------------------------------------------------------------------------
#define HCBLKS 2048
#define XBLKS  1024

__global__ __launch_bounds__(256)
void convert_kernel(const float* __restrict__ hw, const float* __restrict__ x) {
    const int bid = blockIdx.x;
    const int tid = threadIdx.x;
    if (bid < HCBLKS) {
        const size_t base = ((size_t)bid * 256 + tid) * 8;
        const float4 v0 = *(const float4*)(hw + base);
        const float4 v1 = *(const float4*)(hw + base + 4);
        __half2 h[4];
        h[0] = __floats2half2_rn(v0.x, v0.y);
        h[1] = __floats2half2_rn(v0.z, v0.w);
        h[2] = __floats2half2_rn(v1.x, v1.y);
        h[3] = __floats2half2_rn(v1.z, v1.w);
        *(uint4*)(g_hwf16 + base) = *(const uint4*)h;
    } else {
        const int xb = bid - HCBLKS;
        const float4* src = (const float4*)x + (size_t)xb * 1024;
        __half2* dst = (__half2*)g_xh + (size_t)xb * 2048;
#pragma unroll
        for (int i = 0; i < 4; i++) {
            const int e = tid + i * 256;
            const float4 v = src[e];
            dst[e * 2]     = __floats2half2_rn(v.x, v.y);
            dst[e * 2 + 1] = __floats2half2_rn(v.z, v.w);
        }
    }
}

// ---------------------------------------------------------------------------
// Kernel 1: W hash-gather (fp16 source) -> row-major g_wh, full 128B rows.
// Each block: two adjacent n-tiles (same kt); 2B coalesced gather loads,
// smem staging, 16B fully-populated row stores.
// ---------------------------------------------------------------------------
#define WBLKS (256 * 128)    // 32768: kt 0..255, j 0..127 (nt pair = 2j, 2j+1)

__global__ __launch_bounds__(256)
void gather_kernel(const int* __restrict__ rn) {
    __shared__ __half sh[32][64];
    const int bid = blockIdx.x;
    const int tid = threadIdx.x;
    const int kt = bid >> 7, j = bid & 127;
    long long R1, R2, R3;
    decode_rn(rn, R1, R2, R3);
    long long v0 = ((long long)kt * R3 + (long long)(2 * j) * R2 + R1) % P_HASH;
    long long v1 = ((long long)kt * R3 + (long long)(2 * j + 1) * R2 + R1) % P_HASH;
    const int S0 = (int)(v0 % HASH_RANGE);
    const int S1 = (int)(v1 % HASH_RANGE);
    // phase 1: coalesced fp16 gather (2B lane-consecutive) -> smem
#pragma unroll
    for (int i = 0; i < 4; i++) {
        const int e = tid + i * 256;           // 0..1023 = k*32 + n
        sh[e >> 5][e & 31]        = g_hwf16[S0 + e];
        sh[e >> 5][32 + (e & 31)] = g_hwf16[S1 + e];
    }
    __syncthreads();
    // phase 2: 256 chunks of 16B = 32 rows x 128B, fully coalesced
    const int r = tid >> 3, c8 = (tid & 7) * 8;
    const uint4 vle = *(const uint4*)&sh[r][c8];
    *(uint4*)(g_wh + (size_t)(kt * 32 + r) * DIM_N + j * 64 + c8) = vle;
}

// ---------------------------------------------------------------------------
// GEMM kernel: fp16 HMMA (R8 geometry: 8 warps 2x4, warp tile 64x32, JIT
// fragments, PIPE=3, 2 CTAs/SM) with 3-slot mbarrier producer/consumer chain
// (R15/R16, byte-identical): arrive(W[t%3]) at stage end releases slot-t
// reads AND certifies slot t+1; wait acquires both.
// ---------------------------------------------------------------------------
__global__ __launch_bounds__(THREADS, 2)
void rz_f16_kernel(const float* __restrict__ bias,
                   float* __restrict__ out) {
    extern __shared__ char smem[];
    const uint32_t smem_base = smem_to_u32(smem);
    const int tid  = threadIdx.x;
    const int lane = tid & 31;
    const int wid  = tid >> 5;         // 0..7
    const int wm   = wid >> 2;         // 0..1
    const int wn   = wid & 3;          // 0..3
    const int m0   = blockIdx.y * 128;
    const int n0   = blockIdx.x * 128;
    const uint32_t mb = smem_base + OFF_MBAR;

    if (tid == 0) {
        MBARRIER_INIT(mb + 0, THREADS);
        MBARRIER_INIT(mb + 8, THREADS);
        MBARRIER_INIT(mb + 16, THREADS);
    }
    __syncthreads();                   // one-time: mbarriers visible

    auto issue = [&](int t) {
        const int slot = t % PIPE;
        const uint32_t As = smem_base + OFF_A(slot);
        const uint32_t Bs = smem_base + OFF_B(slot);
        const __half* xa = g_xh + (size_t)m0 * DIM_K + t * 64;
        const __half* wb = g_wh + (size_t)(t * 64) * DIM_N + n0;
#pragma unroll
        for (int u = 0; u < 4; u++) {              // A: 1024 16B chunks
            const int ch = tid + u * THREADS;
            const int m = ch >> 3, c = ch & 7;
            cp_async_16(As + m * 128 + ((c ^ (m & 7)) << 4),
                        xa + (size_t)m * DIM_K + c * 8);
        }
#pragma unroll
        for (int u = 0; u < 4; u++) {              // B: 1024 16B chunks
            const int ch = tid + u * THREADS;
            const int k = ch >> 4, c = ch & 15;
            cp_async_16(Bs + k * 256 + ((c ^ (k & 7)) << 4),
                        wb + (size_t)k * DIM_N + c * 8);
        }
    };

    float acc[4][4][4];
#pragma unroll
    for (int mt = 0; mt < 4; mt++)
#pragma unroll
        for (int nt = 0; nt < 4; nt++)
#pragma unroll
            for (int j = 0; j < 4; j++) acc[mt][nt][j] = 0.0f;

    // fragment lane addressing (constant across stages)
    const int ar = (lane & 15);            // A row within 16
    const int ac = (lane >> 4);            // A chunk parity
    const int bk = (lane & 7) + ((lane >> 3) & 1) * 8;   // B k within 16
    const int bc = (lane >> 4);            // B n-chunk parity

    // Prologue: stages 0,1 in flight; certify slot 0 and arrive W[2]
    issue(0); cp_async_commit();
    issue(1); cp_async_commit();
    cp_async_wait<1>();                    // slot 0 complete (this thread)
    MBARRIER_ARRIVE(mb + 16);              // W[2] phase 0

    for (int t = 0; t < NSTG; t++) {
        const int wslot = (t + 2) % 3;     // == (t-1)%3: slot being rewritten
        const int wpar  = (t / 3) & 1;
        MBARRIER_WAIT_PARITY(mb + wslot * 8, wpar);  // readers done + slot t visible

        if (t + 2 < NSTG) issue(t + 2);
        cp_async_commit();                 // possibly empty: fixed group accounting

        const int slot = t % PIPE;
        const uint32_t As = smem_base + OFF_A(slot);
        const uint32_t Bs = smem_base + OFF_B(slot);
#pragma unroll
        for (int g = 0; g < 4; g++) {
            uint32_t a[4][4];
#pragma unroll
            for (int mt = 0; mt < 4; mt++) {
                const int row = wm * 64 + mt * 16 + ar;
                const int ch  = g * 2 + ac;
                ldsm_x4(a[mt], As + row * 128 + ((ch ^ (row & 7)) << 4));
            }
            uint32_t bf[2][4];
#pragma unroll
            for (int ntp = 0; ntp < 2; ntp++) {
                const int k   = g * 16 + bk;
                const int nch = wn * 4 + ntp * 2 + bc;
                ldsm_x4_t(bf[ntp], Bs + k * 256 + ((nch ^ (k & 7)) << 4));
            }
#pragma unroll
            for (int mt = 0; mt < 4; mt++)
#pragma unroll
                for (int nt = 0; nt < 4; nt++)
                    mma_f16(acc[mt][nt], a[mt],
                            bf[nt >> 1][(nt & 1) * 2], bf[nt >> 1][(nt & 1) * 2 + 1]);
        }

        cp_async_wait<1>();                // slot t+1 complete (this thread)
        MBARRIER_ARRIVE(mb + slot * 8);    // release: slot-t reads done + t+1 certified
    }

    // Epilogue
#pragma unroll
    for (int mt = 0; mt < 4; mt++) {
#pragma unroll
        for (int nt = 0; nt < 4; nt++) {
            const int m = m0 + wm * 64 + mt * 16 + (lane >> 2);
            const int n = n0 + wn * 32 + nt * 8 + (lane & 3) * 2;
            const float2 b = *(const float2*)&bias[n];
            float2 o0, o1;
            o0.x = acc[mt][nt][0] + b.x;  o0.y = acc[mt][nt][1] + b.y;
            o1.x = acc[mt][nt][2] + b.x;  o1.y = acc[mt][nt][3] + b.y;
            *(float2*)&out[(size_t)m * DIM_N + n]       = o0;
            *(float2*)&out[(size_t)(m + 8) * DIM_N + n] = o1;
        }
    }
}

// ---------------------------------------------------------------------------
// Launch
// ---------------------------------------------------------------------------
extern "C" void kernel_launch(void* const* d_in, const int* in_sizes, int n_in,
                              void* d_out, int out_size) {
    const float* x    = (const float*)d_in[0];
    const float* hw   = (const float*)d_in[1];
    const float* bias = (const float*)d_in[2];
    const int*   rn   = (const int*)d_in[3];
    float*       out  = (float*)d_out;

    convert_kernel<<<HCBLKS + XBLKS, 256>>>(hw, x);
    gather_kernel<<<WBLKS, 256>>>(rn);

    cudaFuncSetAttribute(rz_f16_kernel, cudaFuncAttributeMaxDynamicSharedMemorySize, SMEM_TOTAL);
    rz_f16_kernel<<<dim3(DIM_N / 128, TOKENS / 128), THREADS, SMEM_TOTAL>>>(bias, out);
}